// round 16
// baseline (speedup 1.0000x reference)
#include <cuda_runtime.h>
#include <cuda_fp16.h>
#include <cstdint>

// Problem constants (fixed by the dataset)
constexpr int B  = 8;
constexpr int NN = 10000;
constexpr int E  = 160000;
constexpr int F  = 128;   // GCN feature dim
constexpr int H  = 256;   // hidden dim
constexpr int BNN = B * NN;          // 80000 rows
constexpr int BE  = B * E;           // 1.28M edges
constexpr int NBLK = (BNN + 255) / 256;   // 313 scan blocks
constexpr float NEG_SLOPE = 0.01f;

// Split point for gather/fused23 overlap
constexpr int BLKS   = BNN / 128;        // 625
constexpr int BLKS0  = 312;              // first half blocks
constexpr int ROWS0  = BLKS0 * 128;      // 39936

// Scratch (allocation-free: __device__ globals)
__device__ float  g_dinv[BNN];
__device__ int    g_degi[BNN];
__device__ int    g_rowoff[BNN];
__device__ int    g_cursor[BNN];
__device__ int    g_bsum[512];
__device__ int    g_csr_src[BE];
__device__ float  g_csr_norm[BE];
__device__ __half g_xwh[(size_t)BNN * F];     // fp16 xw (gather source)
__device__ __half g_x0h[(size_t)BNN * F];     // fp16 x0
__device__ __half g_o1h[(size_t)BNN * F];     // fp16 out1
__device__ __half g_wch[F * F];               // Wc^T fp16 [N][K]
__device__ __half g_w1h[H * F];               // W1^T fp16 [N][K]
__device__ __half g_w2h[H * H];               // W2^T fp16 [N][K]

__device__ __forceinline__ void mma_f16(float c[4], uint32_t a0, uint32_t a1,
                                        uint32_t a2, uint32_t a3,
                                        uint32_t b0, uint32_t b1) {
    asm volatile(
        "mma.sync.aligned.m16n8k16.row.col.f32.f16.f16.f32 "
        "{%0,%1,%2,%3}, {%4,%5,%6,%7}, {%8,%9}, {%0,%1,%2,%3};"
        : "+f"(c[0]), "+f"(c[1]), "+f"(c[2]), "+f"(c[3])
        : "r"(a0), "r"(a1), "r"(a2), "r"(a3), "r"(b0), "r"(b1));
}
__device__ __forceinline__ void ldsm4(uint32_t& r0, uint32_t& r1,
                                      uint32_t& r2, uint32_t& r3, uint32_t addr) {
    asm volatile("ldmatrix.sync.aligned.m8n8.x4.shared.b16 {%0,%1,%2,%3}, [%4];"
                 : "=r"(r0), "=r"(r1), "=r"(r2), "=r"(r3) : "r"(addr));
}
__device__ __forceinline__ void ldsm2(uint32_t& r0, uint32_t& r1, uint32_t addr) {
    asm volatile("ldmatrix.sync.aligned.m8n8.x2.shared.b16 {%0,%1}, [%2];"
                 : "=r"(r0), "=r"(r1) : "r"(addr));
}

// ---------------------------------------------------------------------------
// Degree / CSR build
// ---------------------------------------------------------------------------
__global__ void zero_deg_kernel() {
    int i = blockIdx.x * blockDim.x + threadIdx.x;
    if (i < BNN) g_degi[i] = 0;
}
__global__ void hist_kernel(const int* __restrict__ ei) {
    int i = blockIdx.x * blockDim.x + threadIdx.x;
    if (i >= BE) return;
    int b = i / E;
    int e = i - b * E;
    int dst = ei[b * 2 * E + E + e];
    atomicAdd(&g_degi[b * NN + dst], 1);
}
__global__ void dinv_kernel() {
    int i = blockIdx.x * blockDim.x + threadIdx.x;
    if (i < BNN) g_dinv[i] = rsqrtf(1.0f + (float)g_degi[i]);   // +1 self loop
}
__global__ void scan1_kernel() {
    __shared__ int sh[256];
    int i = blockIdx.x * 256 + threadIdx.x;
    int v = (i < BNN) ? g_degi[i] : 0;
    sh[threadIdx.x] = v;
    __syncthreads();
    #pragma unroll
    for (int off = 1; off < 256; off <<= 1) {
        int t = (threadIdx.x >= off) ? sh[threadIdx.x - off] : 0;
        __syncthreads();
        sh[threadIdx.x] += t;
        __syncthreads();
    }
    if (i < BNN) g_rowoff[i] = sh[threadIdx.x] - v;
    if (threadIdx.x == 255) g_bsum[blockIdx.x] = sh[255];
}
__global__ void scan2_kernel() {
    __shared__ int sh[512];
    int t = threadIdx.x;
    int v = (t < NBLK) ? g_bsum[t] : 0;
    sh[t] = v;
    __syncthreads();
    #pragma unroll
    for (int off = 1; off < 512; off <<= 1) {
        int u = (t >= off) ? sh[t - off] : 0;
        __syncthreads();
        sh[t] += u;
        __syncthreads();
    }
    g_bsum[t] = sh[t] - v;   // exclusive
}
__global__ void scan3_kernel() {
    int i = blockIdx.x * blockDim.x + threadIdx.x;
    if (i >= BNN) return;
    int off = g_rowoff[i] + g_bsum[i >> 8];
    g_rowoff[i] = off;
    g_cursor[i] = off;
}
__global__ void fill_kernel(const int* __restrict__ ei) {
    int i = blockIdx.x * blockDim.x + threadIdx.x;
    if (i >= BE) return;
    int b = i / E;
    int e = i - b * E;
    const int* eb = ei + b * 2 * E;
    int gs = b * NN + eb[e];
    int gd = b * NN + eb[E + e];
    int pos = atomicAdd(&g_cursor[gd], 1);
    g_csr_src[pos]  = gs;
    g_csr_norm[pos] = g_dinv[gs] * g_dinv[gd];
}

// ---------------------------------------------------------------------------
// Weight / input conversion
// ---------------------------------------------------------------------------
__global__ void transpose_f16_kernel(const float* __restrict__ W, __half* __restrict__ Wt,
                                     int K, int N) {
    int i = blockIdx.x * blockDim.x + threadIdx.x;
    if (i >= K * N) return;
    int k = i / N, n = i % N;
    Wt[(size_t)n * K + k] = __float2half_rn(W[i]);
}
__global__ void cvt_f16_kernel(const float* __restrict__ in, __half* __restrict__ out, int n4) {
    int i = blockIdx.x * blockDim.x + threadIdx.x;
    if (i >= n4) return;
    float4 v = ((const float4*)in)[i];
    __half2 h01 = __floats2half2_rn(v.x, v.y);
    __half2 h23 = __floats2half2_rn(v.z, v.w);
    uint2 st;
    st.x = *(uint32_t*)&h01;
    st.y = *(uint32_t*)&h23;
    ((uint2*)out)[i] = st;
}

// ---------------------------------------------------------------------------
// FP16 GEMM (single layer): cp.async 3-stage + ldmatrix, plain fp16 out.
// ---------------------------------------------------------------------------
constexpr int STAGE_BYTES = 16384;
constexpr int GEMM_SMEM   = 3 * STAGE_BYTES;

__global__ __launch_bounds__(256, 2)
void f16_gemm_kernel(const __half* __restrict__ At, const __half* __restrict__ Bt,
                     __half* __restrict__ Ch, int M, int Nn, int K) {
    extern __shared__ uint32_t sh[];

    const int tid  = threadIdx.x;
    const int lane = tid & 31;
    const int wid  = tid >> 5;
    const int wm   = wid & 1;
    const int wn   = wid >> 1;
    const int bx = blockIdx.x, by = blockIdx.y;

    const __half* Ablk = At + (size_t)by * 128 * K;
    const __half* Bblk = Bt + (size_t)bx * 128 * K;

    float acc[4][4][4];
    #pragma unroll
    for (int i = 0; i < 4; i++)
        #pragma unroll
        for (int j = 0; j < 4; j++)
            #pragma unroll
            for (int q = 0; q < 4; q++) acc[i][j][q] = 0.0f;

    const uint32_t sbase = (uint32_t)__cvta_generic_to_shared(sh);
    const int sRow = tid >> 1;
    const int sC2  = (tid & 1) * 2;

    auto issue = [&](int st, int kt) {
        uint32_t abase = sbase + st * STAGE_BYTES;
        uint32_t bbase = abase + 8192;
        #pragma unroll
        for (int q = 0; q < 2; q++) {
            int c = sC2 + q;
            uint32_t doff = sRow * 64 + ((c ^ ((sRow >> 1) & 3)) << 4);
            asm volatile("cp.async.cg.shared.global [%0], [%1], 16;"
                         :: "r"(abase + doff), "l"(Ablk + (size_t)sRow * K + kt + c * 8));
            asm volatile("cp.async.cg.shared.global [%0], [%1], 16;"
                         :: "r"(bbase + doff), "l"(Bblk + (size_t)sRow * K + kt + c * 8));
        }
    };
    auto compute = [&](int st) {
        uint32_t abase = sbase + st * STAGE_BYTES;
        uint32_t bbase = abase + 8192;
        #pragma unroll
        for (int s = 0; s < 2; s++) {
            uint32_t af[4][4];
            uint32_t bf[4][2];
            #pragma unroll
            for (int i = 0; i < 4; i++) {
                int row = wm * 64 + i * 16 + (lane & 7) + ((lane >> 3) & 1) * 8;
                int ch  = 2 * s + (lane >> 4);
                ldsm4(af[i][0], af[i][1], af[i][2], af[i][3],
                      abase + row * 64 + ((ch ^ ((row >> 1) & 3)) << 4));
            }
            #pragma unroll
            for (int j = 0; j < 4; j++) {
                int row = wn * 32 + j * 8 + (lane & 7);
                int ch  = 2 * s + ((lane >> 3) & 1);
                ldsm2(bf[j][0], bf[j][1],
                      bbase + row * 64 + ((ch ^ ((row >> 1) & 3)) << 4));
            }
            #pragma unroll
            for (int i = 0; i < 4; i++)
                #pragma unroll
                for (int j = 0; j < 4; j++)
                    mma_f16(acc[i][j], af[i][0], af[i][1], af[i][2], af[i][3],
                            bf[j][0], bf[j][1]);
        }
    };

    const int CH = K / 32;
    issue(0, 0);
    asm volatile("cp.async.commit_group;" ::: "memory");
    issue(1, 32);
    asm volatile("cp.async.commit_group;" ::: "memory");
    for (int c = 0; c < CH; c++) {
        asm volatile("cp.async.wait_group 1;" ::: "memory");
        __syncthreads();
        if (c + 2 < CH) issue((c + 2) % 3, (c + 2) * 32);
        asm volatile("cp.async.commit_group;" ::: "memory");
        compute(c % 3);
    }

    #pragma unroll
    for (int i = 0; i < 4; i++)
        #pragma unroll
        for (int j = 0; j < 4; j++) {
            int col = wn * 32 + j * 8 + 2 * (lane & 3);
            #pragma unroll
            for (int h = 0; h < 2; h++) {
                int row = wm * 64 + i * 16 + (lane >> 2) + h * 8;
                __half2 hv = __floats2half2_rn(acc[i][j][h * 2], acc[i][j][h * 2 + 1]);
                *(uint32_t*)(Ch + (size_t)(by * 128 + row) * Nn + bx * 128 + col) = *(uint32_t*)&hv;
            }
        }
}

// ---------------------------------------------------------------------------
// Fused GEMM2+GEMM3 (block range [blk0, blk0+gridDim.x)): h1 kept in smem.
// ---------------------------------------------------------------------------
constexpr int H1_BYTES   = 128 * 512;                 // 65536
constexpr int F23_SMEM   = H1_BYTES + GEMM_SMEM;      // 114688

__global__ __launch_bounds__(256, 2)
void fused23_kernel(const __half* __restrict__ o1h, const __half* __restrict__ w1h,
                    const __half* __restrict__ w2h, const float* __restrict__ b1,
                    const float* __restrict__ b2, float* __restrict__ out, int blk0) {
    extern __shared__ uint32_t sh[];

    const int tid  = threadIdx.x;
    const int lane = tid & 31;
    const int wid  = tid >> 5;
    const int wm   = wid & 1;
    const int wn   = wid >> 1;
    const int by = blockIdx.x + blk0;

    const uint32_t sbase  = (uint32_t)__cvta_generic_to_shared(sh);
    const uint32_t h1base = sbase;
    const uint32_t stbase = sbase + H1_BYTES;
    const int sRow = tid >> 1;
    const int sC2  = (tid & 1) * 2;

    float acc[4][4][4];

    const __half* Ablk = o1h + (size_t)by * 128 * F;

    // ---------------- Phase 1: h1 = leaky(o1 @ W1 + b1) -> smem ----------------
    #pragma unroll 1
    for (int half = 0; half < 2; half++) {
        #pragma unroll
        for (int i = 0; i < 4; i++)
            #pragma unroll
            for (int j = 0; j < 4; j++)
                #pragma unroll
                for (int q = 0; q < 4; q++) acc[i][j][q] = 0.0f;

        const __half* Bblk = w1h + (size_t)half * 128 * F;

        auto issue1 = [&](int st, int kt) {
            uint32_t abase = stbase + st * STAGE_BYTES;
            uint32_t bbase = abase + 8192;
            #pragma unroll
            for (int q = 0; q < 2; q++) {
                int c = sC2 + q;
                uint32_t doff = sRow * 64 + ((c ^ ((sRow >> 1) & 3)) << 4);
                asm volatile("cp.async.cg.shared.global [%0], [%1], 16;"
                             :: "r"(abase + doff), "l"(Ablk + (size_t)sRow * F + kt + c * 8));
                asm volatile("cp.async.cg.shared.global [%0], [%1], 16;"
                             :: "r"(bbase + doff), "l"(Bblk + (size_t)sRow * F + kt + c * 8));
            }
        };
        auto compute1 = [&](int st) {
            uint32_t abase = stbase + st * STAGE_BYTES;
            uint32_t bbase = abase + 8192;
            #pragma unroll
            for (int s = 0; s < 2; s++) {
                uint32_t af[4][4], bf[4][2];
                #pragma unroll
                for (int i = 0; i < 4; i++) {
                    int row = wm * 64 + i * 16 + (lane & 7) + ((lane >> 3) & 1) * 8;
                    int ch  = 2 * s + (lane >> 4);
                    ldsm4(af[i][0], af[i][1], af[i][2], af[i][3],
                          abase + row * 64 + ((ch ^ ((row >> 1) & 3)) << 4));
                }
                #pragma unroll
                for (int j = 0; j < 4; j++) {
                    int row = wn * 32 + j * 8 + (lane & 7);
                    int ch  = 2 * s + ((lane >> 3) & 1);
                    ldsm2(bf[j][0], bf[j][1],
                          bbase + row * 64 + ((ch ^ ((row >> 1) & 3)) << 4));
                }
                #pragma unroll
                for (int i = 0; i < 4; i++)
                    #pragma unroll
                    for (int j = 0; j < 4; j++)
                        mma_f16(acc[i][j], af[i][0], af[i][1], af[i][2], af[i][3],
                                bf[j][0], bf[j][1]);
            }
        };

        issue1(0, 0);
        asm volatile("cp.async.commit_group;" ::: "memory");
        issue1(1, 32);
        asm volatile("cp.async.commit_group;" ::: "memory");
        for (int c = 0; c < 4; c++) {
            asm volatile("cp.async.wait_group 1;" ::: "memory");
            __syncthreads();
            if (c + 2 < 4) issue1((c + 2) % 3, (c + 2) * 32);
            asm volatile("cp.async.commit_group;" ::: "memory");
            compute1(c % 3);
        }
        __syncthreads();

        // epilogue -> smem h1buf (fp16, swizzle ch ^ (row&7) on 512B rows)
        #pragma unroll
        for (int i = 0; i < 4; i++)
            #pragma unroll
            for (int j = 0; j < 4; j++) {
                int gcol = half * 128 + wn * 32 + j * 8 + 2 * (lane & 3);
                int ch16 = gcol >> 3;
                float bx0 = b1[gcol], bx1 = b1[gcol + 1];
                #pragma unroll
                for (int h = 0; h < 2; h++) {
                    int row = wm * 64 + i * 16 + (lane >> 2) + h * 8;
                    float vx = acc[i][j][h * 2] + bx0;
                    float vy = acc[i][j][h * 2 + 1] + bx1;
                    vx = vx > 0.0f ? vx : NEG_SLOPE * vx;
                    vy = vy > 0.0f ? vy : NEG_SLOPE * vy;
                    __half2 hv = __floats2half2_rn(vx, vy);
                    uint32_t addr = h1base + row * 512 + ((ch16 ^ (row & 7)) << 4)
                                  + (gcol & 7) * 2;
                    asm volatile("st.shared.b32 [%0], %1;" :: "r"(addr), "r"(*(uint32_t*)&hv));
                }
            }
        __syncthreads();
    }

    // ---------------- Phase 2: out = leaky(h1 @ W2 + b2) ----------------
    #pragma unroll 1
    for (int outhalf = 0; outhalf < 2; outhalf++) {
        #pragma unroll
        for (int i = 0; i < 4; i++)
            #pragma unroll
            for (int j = 0; j < 4; j++)
                #pragma unroll
                for (int q = 0; q < 4; q++) acc[i][j][q] = 0.0f;

        const __half* Bblk = w2h + (size_t)outhalf * 128 * H;

        auto issue2 = [&](int st, int kt) {
            uint32_t bbase = stbase + st * STAGE_BYTES;   // B-only stage
            #pragma unroll
            for (int q = 0; q < 2; q++) {
                int c = sC2 + q;
                uint32_t doff = sRow * 64 + ((c ^ ((sRow >> 1) & 3)) << 4);
                asm volatile("cp.async.cg.shared.global [%0], [%1], 16;"
                             :: "r"(bbase + doff), "l"(Bblk + (size_t)sRow * H + kt + c * 8));
            }
        };
        auto compute2 = [&](int st, int kc) {
            uint32_t bbase = stbase + st * STAGE_BYTES;
            #pragma unroll
            for (int s = 0; s < 2; s++) {
                uint32_t af[4][4], bf[4][2];
                #pragma unroll
                for (int i = 0; i < 4; i++) {
                    int row = wm * 64 + i * 16 + (lane & 7) + ((lane >> 3) & 1) * 8;
                    int ch  = kc * 4 + 2 * s + (lane >> 4);
                    ldsm4(af[i][0], af[i][1], af[i][2], af[i][3],
                          h1base + row * 512 + ((ch ^ (row & 7)) << 4));
                }
                #pragma unroll
                for (int j = 0; j < 4; j++) {
                    int row = wn * 32 + j * 8 + (lane & 7);
                    int ch  = 2 * s + ((lane >> 3) & 1);
                    ldsm2(bf[j][0], bf[j][1],
                          bbase + row * 64 + ((ch ^ ((row >> 1) & 3)) << 4));
                }
                #pragma unroll
                for (int i = 0; i < 4; i++)
                    #pragma unroll
                    for (int j = 0; j < 4; j++)
                        mma_f16(acc[i][j], af[i][0], af[i][1], af[i][2], af[i][3],
                                bf[j][0], bf[j][1]);
            }
        };

        issue2(0, 0);
        asm volatile("cp.async.commit_group;" ::: "memory");
        issue2(1, 32);
        asm volatile("cp.async.commit_group;" ::: "memory");
        for (int c = 0; c < 8; c++) {
            asm volatile("cp.async.wait_group 1;" ::: "memory");
            __syncthreads();
            if (c + 2 < 8) issue2((c + 2) % 3, (c + 2) * 32);
            asm volatile("cp.async.commit_group;" ::: "memory");
            compute2(c % 3, c);
        }
        __syncthreads();

        #pragma unroll
        for (int i = 0; i < 4; i++)
            #pragma unroll
            for (int j = 0; j < 4; j++) {
                int gcol = outhalf * 128 + wn * 32 + j * 8 + 2 * (lane & 3);
                float bx0 = b2[gcol], bx1 = b2[gcol + 1];
                #pragma unroll
                for (int h = 0; h < 2; h++) {
                    int row = wm * 64 + i * 16 + (lane >> 2) + h * 8;
                    float vx = acc[i][j][h * 2] + bx0;
                    float vy = acc[i][j][h * 2 + 1] + bx1;
                    vx = vx > 0.0f ? vx : NEG_SLOPE * vx;
                    vy = vy > 0.0f ? vy : NEG_SLOPE * vy;
                    *(float2*)(out + (size_t)(by * 128 + row) * H + gcol) = make_float2(vx, vy);
                }
            }
    }
}

// ---------------------------------------------------------------------------
// Gather-aggregate + fused post (rows [row0, row0+nrows)): one warp per row.
// ---------------------------------------------------------------------------
__global__ __launch_bounds__(256)
void gather_kernel(const float* __restrict__ bc, int row0, int nrows) {
    int wl = (blockIdx.x * blockDim.x + threadIdx.x) >> 5;
    int lane = threadIdx.x & 31;
    if (wl >= nrows) return;
    int w = row0 + wl;

    float dd = g_dinv[w];
    float selfs = dd * dd;
    uint2 sv = ((const uint2*)(g_xwh + (size_t)w * F))[lane];
    float2 s01 = __half22float2(*(__half2*)&sv.x);
    float2 s23 = __half22float2(*(__half2*)&sv.y);
    float a0 = selfs * s01.x, a1 = selfs * s01.y;
    float a2 = selfs * s23.x, a3 = selfs * s23.y;

    int kbeg = g_rowoff[w];
    int kend = (w + 1 < BNN) ? g_rowoff[w + 1] : BE;
    for (int k = kbeg; k < kend; k++) {
        int gs = g_csr_src[k];
        float nm = g_csr_norm[k];
        uint2 v = ((const uint2*)(g_xwh + (size_t)gs * F))[lane];
        float2 f01 = __half22float2(*(__half2*)&v.x);
        float2 f23 = __half22float2(*(__half2*)&v.y);
        a0 = fmaf(nm, f01.x, a0);
        a1 = fmaf(nm, f01.y, a1);
        a2 = fmaf(nm, f23.x, a2);
        a3 = fmaf(nm, f23.y, a3);
    }

    float4 bb = ((const float4*)bc)[lane];
    uint2 xh = ((const uint2*)(g_x0h + (size_t)w * F))[lane];
    float2 x01 = __half22float2(*(__half2*)&xh.x);
    float2 x23 = __half22float2(*(__half2*)&xh.y);
    float o0 = fmaxf(a0 + bb.x, 0.0f) + x01.x;
    float o1 = fmaxf(a1 + bb.y, 0.0f) + x01.y;
    float o2 = fmaxf(a2 + bb.z, 0.0f) + x23.x;
    float o3 = fmaxf(a3 + bb.w, 0.0f) + x23.y;
    __half2 h01 = __floats2half2_rn(o0, o1);
    __half2 h23 = __floats2half2_rn(o2, o3);
    uint2 st;
    st.x = *(uint32_t*)&h01;
    st.y = *(uint32_t*)&h23;
    ((uint2*)(g_o1h + (size_t)w * F))[lane] = st;
}

// ---------------------------------------------------------------------------
extern "C" void kernel_launch(void* const* d_in, const int* in_sizes, int n_in,
                              void* d_out, int out_size) {
    const float* x0 = (const float*)d_in[0];       // [B,N,F]
    const int*   ei = (const int*)d_in[1];         // [B,2,E] int32
    const float* Wc = (const float*)d_in[2];       // [F,F]
    const float* bc = (const float*)d_in[3];       // [F]
    const float* W1 = (const float*)d_in[4];       // [F,H]
    const float* b1 = (const float*)d_in[5];       // [H]
    const float* W2 = (const float*)d_in[6];       // [H,H]
    const float* b2 = (const float*)d_in[7];       // [H]
    float* out = (float*)d_out;                    // [B,N,H]

    __half *xwh, *x0h, *o1h, *wch, *w1h, *w2h;
    cudaGetSymbolAddress((void**)&xwh,  g_xwh);
    cudaGetSymbolAddress((void**)&x0h,  g_x0h);
    cudaGetSymbolAddress((void**)&o1h,  g_o1h);
    cudaGetSymbolAddress((void**)&wch,  g_wch);
    cudaGetSymbolAddress((void**)&w1h,  g_w1h);
    cudaGetSymbolAddress((void**)&w2h,  g_w2h);

    static bool init_done = false;
    static cudaStream_t s1;
    static cudaEvent_t evFork, evJoin, evG, evJ1;
    if (!init_done) {
        cudaFuncSetAttribute(f16_gemm_kernel, cudaFuncAttributeMaxDynamicSharedMemorySize, GEMM_SMEM);
        cudaFuncSetAttribute(fused23_kernel, cudaFuncAttributeMaxDynamicSharedMemorySize, F23_SMEM);
        cudaStreamCreateWithFlags(&s1, cudaStreamNonBlocking);
        cudaEventCreateWithFlags(&evFork, cudaEventDisableTiming);
        cudaEventCreateWithFlags(&evJoin, cudaEventDisableTiming);
        cudaEventCreateWithFlags(&evG, cudaEventDisableTiming);
        cudaEventCreateWithFlags(&evJ1, cudaEventDisableTiming);
        init_done = true;
    }

    // Fork: side chain on s1 (W1/W2 transposes + CSR build; none on critical path)
    cudaEventRecord(evFork, 0);
    cudaStreamWaitEvent(s1, evFork, 0);
    transpose_f16_kernel<<<(F * H + 255) / 256, 256, 0, s1>>>(W1, w1h, F, H);
    transpose_f16_kernel<<<(H * H + 255) / 256, 256, 0, s1>>>(W2, w2h, H, H);
    zero_deg_kernel<<<NBLK, 256, 0, s1>>>();
    hist_kernel<<<(BE + 255) / 256, 256, 0, s1>>>(ei);
    dinv_kernel<<<NBLK, 256, 0, s1>>>();
    scan1_kernel<<<NBLK, 256, 0, s1>>>();
    scan2_kernel<<<1, 512, 0, s1>>>();
    scan3_kernel<<<NBLK, 256, 0, s1>>>();
    fill_kernel<<<(BE + 255) / 256, 256, 0, s1>>>(ei);
    cudaEventRecord(evJoin, s1);

    // Main chain: Wc transpose, x0 cvt, GEMM1
    transpose_f16_kernel<<<(F * F + 255) / 256, 256>>>(Wc, wch, F, F);
    cvt_f16_kernel<<<(BNN * F / 4 + 255) / 256, 256>>>(x0, x0h, BNN * F / 4);
    {
        dim3 grid(1, BNN / 128);
        f16_gemm_kernel<<<grid, 256, GEMM_SMEM>>>(x0h, wch, xwh, BNN, F, F);
    }
    cudaEventRecord(evG, 0);   // xwh ready

    // s1: second-half gather (needs CSR chain on s1 + xwh from stream 0)
    cudaStreamWaitEvent(s1, evG, 0);
    gather_kernel<<<((BNN - ROWS0) * 32 + 255) / 256, 256, 0, s1>>>(bc, ROWS0, BNN - ROWS0);
    cudaEventRecord(evJ1, s1);

    // Stream 0: first-half gather (needs CSR + weights from s1 -> evJoin)
    cudaStreamWaitEvent(0, evJoin, 0);
    gather_kernel<<<(ROWS0 * 32 + 255) / 256, 256>>>(bc, 0, ROWS0);

    // fused23 first half overlaps with gather of second half on s1
    fused23_kernel<<<BLKS0, 256, F23_SMEM>>>(o1h, w1h, w2h, b1, b2, out, 0);

    // join and finish second half
    cudaStreamWaitEvent(0, evJ1, 0);
    fused23_kernel<<<BLKS - BLKS0, 256, F23_SMEM>>>(o1h, w1h, w2h, b1, b2, out, BLKS0);
}